// round 16
// baseline (speedup 1.0000x reference)
#include <cuda_runtime.h>
#include <cuda_fp16.h>
#include <math.h>
#include <math_constants.h>
#include <stdint.h>

#define BS_  2
#define SEQ  2048
#define DM   768
#define FF   3072
#define NH   12
#define DK   64
#define ROWS (BS_*SEQ)   // 4096

// ---------------- scratch (allocation-free: device globals) ----------------
__device__ __half g_xnh [ROWS*(size_t)DM];
__device__ __half g_qh  [ROWS*(size_t)DM];     // [B,H,S,dk]
__device__ __half g_kh  [ROWS*(size_t)DM];     // [B,H,S,dk]
__device__ __half g_vth [ROWS*(size_t)DM];     // [B,H,dk,S] (transposed V)
__device__ __half g_ctxh[ROWS*(size_t)DM];
__device__ float  g_x1 [ROWS*(size_t)DM];
__device__ __half g_ffh [ROWS*(size_t)FF];
#define WT_QKV 0
#define WT_O   (2304*768)
#define WT_1   (WT_O + 768*768)
#define WT_2   (WT_1 + 3072*768)
__device__ __half g_wth [WT_2 + (size_t)768*3072];
__device__ float  g_bqkv[2304];
__device__ int    g_mflag[(SEQ/128)*(SEQ/64)];

// ================= helpers =================
__device__ __forceinline__ uint32_t smem_u32(const void* p) {
    uint32_t a;
    asm("{ .reg .u64 t; cvta.to.shared.u64 t, %1; cvt.u32.u64 %0, t; }" : "=r"(a) : "l"(p));
    return a;
}
__device__ __forceinline__ void ldsm4(uint32_t* r, uint32_t addr) {
    asm volatile("ldmatrix.sync.aligned.m8n8.x4.shared.b16 {%0,%1,%2,%3}, [%4];"
        : "=r"(r[0]), "=r"(r[1]), "=r"(r[2]), "=r"(r[3]) : "r"(addr));
}
__device__ __forceinline__ uint32_t packh2(float a, float b) {
    __half2 h = __floats2half2_rn(a, b);
    return *(uint32_t*)&h;
}
__device__ __forceinline__ void mma16h(float* d, const uint32_t* a, const uint32_t* b) {
    asm volatile(
        "mma.sync.aligned.m16n8k16.row.col.f32.f16.f16.f32 "
        "{%0,%1,%2,%3}, {%4,%5,%6,%7}, {%8,%9}, {%0,%1,%2,%3};"
        : "+f"(d[0]), "+f"(d[1]), "+f"(d[2]), "+f"(d[3])
        : "r"(a[0]), "r"(a[1]), "r"(a[2]), "r"(a[3]), "r"(b[0]), "r"(b[1]));
}
#define CP_ASYNC16(dst, src) \
    asm volatile("cp.async.cg.shared.global [%0], [%1], 16;" :: "r"(dst), "l"(src))
#define CP_COMMIT() asm volatile("cp.async.commit_group;" ::: "memory")
#define CP_WAIT(n)  asm volatile("cp.async.wait_group %0;" :: "n"(n) : "memory")

// generic exp (unused in hot paths)
__device__ __forceinline__ float fexp(float x) {
    x = fmaxf(x, -87.0f);
    float y = x * 1.4426950408889634f;
    float f = floorf(y);
    float r = y - f;
    float p = 1.5403530393381611e-4f;
    p = fmaf(p, r, 1.3333558146428443e-3f);
    p = fmaf(p, r, 9.6181291076284772e-3f);
    p = fmaf(p, r, 5.5504108664821580e-2f);
    p = fmaf(p, r, 2.4022650695910071e-1f);
    p = fmaf(p, r, 6.9314718055994531e-1f);
    p = fmaf(p, r, 1.0f);
    float sc = __int_as_float(((int)f + 127) << 23);
    return p * sc;
}

// fast 2^y via magic-number round-to-nearest
#define EXP2_KINT (0x4B400000 - (127 << 0))
__device__ __forceinline__ float fexp2m(float y) {
    float t = y + 12582912.f;                 // 1.5 * 2^23
    float r = y - (t - 12582912.f);
    float sc = __int_as_float((__float_as_int(t) - EXP2_KINT) << 23);
    float p = 1.3333558146428443e-3f;
    p = fmaf(p, r, 9.6181291076284772e-3f);
    p = fmaf(p, r, 5.5504108664821580e-2f);
    p = fmaf(p, r, 2.4022650695910071e-1f);
    p = fmaf(p, r, 6.9314718055994531e-1f);
    p = fmaf(p, r, 1.0f);
    return p * sc;
}
#define EXP_C1 0.18033688011112042f
#define EXP_C0 (-11.541560327111707f)

// ================= merged prep: transposes + bias + mask flags + LN1 =================
#define PREP_BLOCKS 11523

__global__ void prep_all(const float* __restrict__ x,
                         const float* __restrict__ alpha1, const float* __restrict__ beta1,
                         const int* __restrict__ mask,
                         const float* __restrict__ wq, const float* __restrict__ wk,
                         const float* __restrict__ wv, const float* __restrict__ wo,
                         const float* __restrict__ w1, const float* __restrict__ w2,
                         const float* __restrict__ bq, const float* __restrict__ bk,
                         const float* __restrict__ bv,
                         __half* __restrict__ wt, float* __restrict__ bqkv,
                         int* __restrict__ flags, __half* __restrict__ xn) {
    __shared__ float sh[32 * 33];
    int bid = blockIdx.x;
    int tid = threadIdx.x;

    if (bid < 6912) {
        int tx = tid & 31, ty = tid >> 5;
        const float* src; __half* dst; int K, N, bx, by;
        if (bid < 2304) {
            int j = bid / 576, loc = bid % 576;
            bx = loc % 24; by = loc / 24; K = 768; N = 768;
            src = (j == 0) ? wq : (j == 1) ? wk : (j == 2) ? wv : wo;
            dst = wt + ((j == 3) ? WT_O : WT_QKV + j * 768 * 768);
        } else if (bid < 4608) {
            int loc = bid - 2304;
            bx = loc % 96; by = loc / 96; K = 768; N = 3072;
            src = w1; dst = wt + WT_1;
        } else {
            int loc = bid - 4608;
            bx = loc % 24; by = loc / 24; K = 3072; N = 768;
            src = w2; dst = wt + WT_2;
        }
        int n0 = bx * 32, k0 = by * 32;
        #pragma unroll
        for (int i = 0; i < 32; i += 8)
            sh[(ty + i) * 33 + tx] =
                src[(size_t)(k0 + ty + i) * N + n0 + tx];
        __syncthreads();
        #pragma unroll
        for (int i = 0; i < 32; i += 8)
            dst[(size_t)(n0 + ty + i) * K + k0 + tx] =
                __float2half(sh[tx * 33 + ty + i]);
    } else if (bid < 6915) {
        int i = (bid - 6912) * 256 + tid;
        if (i < 768) { bqkv[i] = bq[i]; bqkv[768 + i] = bk[i]; bqkv[1536 + i] = bv[i]; }
    } else if (bid < 7427) {
        int mb = bid - 6915;
        int qt = mb >> 5, kt = mb & 31;
        const int* mr = mask + (size_t)(qt * 128 + (tid >> 1)) * SEQ + kt * 64 + (tid & 1) * 32;
        int all = 1;
        #pragma unroll
        for (int i = 0; i < 8; i++) {
            int4 m = *(const int4*)&mr[i * 4];
            all &= (m.x != 0) & (m.y != 0) & (m.z != 0) & (m.w != 0);
        }
        all = __syncthreads_and(all);
        if (tid == 0) flags[mb] = all;
    } else {
        int row = bid - 7427;
        const float* xr = x + (size_t)row * DM;
        float s = 0.f, s2 = 0.f;
        for (int i = tid; i < DM; i += 256) {
            float v = xr[i]; s += v; s2 += v * v;
        }
        #pragma unroll
        for (int o = 16; o; o >>= 1) {
            s  += __shfl_down_sync(0xffffffffu, s,  o);
            s2 += __shfl_down_sync(0xffffffffu, s2, o);
        }
        int w = tid >> 5, l = tid & 31;
        if (l == 0) { sh[w] = s; sh[32 + w] = s2; }
        __syncthreads();
        if (tid == 0) {
            float S = 0.f, S2 = 0.f;
            for (int i = 0; i < 8; i++) { S += sh[i]; S2 += sh[32 + i]; }
            float mean = S / DM;
            float var  = (S2 - DM * mean * mean) / (DM - 1);
            sh[0] = mean;
            sh[1] = rsqrtf(var + 1e-6f);
        }
        __syncthreads();
        float mean = sh[0], inv = sh[1];
        float a = alpha1[0], b = beta1[0];
        __half2* yr = (__half2*)(xn + (size_t)row * DM);
        const float2* xr2 = (const float2*)xr;
        for (int i = tid; i < DM / 2; i += 256) {
            float2 v = xr2[i];
            yr[i] = __floats2half2_rn(a * (v.x - mean) * inv + b,
                                      a * (v.y - mean) * inv + b);
        }
    }
}

// ---------------- LayerNorm (ddof=1) -> fp16 (LN2) ----------------
__global__ void ln_kernel(const float* __restrict__ x,
                          const float* __restrict__ alpha,
                          const float* __restrict__ beta,
                          __half* __restrict__ y) {
    int row = blockIdx.x;
    const float* xr = x + (size_t)row * DM;
    float s = 0.f, s2 = 0.f;
    for (int i = threadIdx.x; i < DM; i += blockDim.x) {
        float v = xr[i]; s += v; s2 += v * v;
    }
    __shared__ float red[64];
    #pragma unroll
    for (int o = 16; o; o >>= 1) {
        s  += __shfl_down_sync(0xffffffffu, s,  o);
        s2 += __shfl_down_sync(0xffffffffu, s2, o);
    }
    int w = threadIdx.x >> 5, l = threadIdx.x & 31;
    if (l == 0) { red[w] = s; red[32 + w] = s2; }
    __syncthreads();
    if (threadIdx.x == 0) {
        float S = 0.f, S2 = 0.f;
        int nw = blockDim.x >> 5;
        for (int i = 0; i < nw; i++) { S += red[i]; S2 += red[32 + i]; }
        float mean = S / DM;
        float var  = (S2 - DM * mean * mean) / (DM - 1);
        red[0] = mean;
        red[1] = rsqrtf(var + 1e-6f);
    }
    __syncthreads();
    float mean = red[0], inv = red[1];
    float a = alpha[0], b = beta[0];
    __half2* yr = (__half2*)(y + (size_t)row * DM);
    const float2* xr2 = (const float2*)xr;
    for (int i = threadIdx.x; i < DM / 2; i += blockDim.x) {
        float2 v = xr2[i];
        yr[i] = __floats2half2_rn(a * (v.x - mean) * inv + b,
                                  a * (v.y - mean) * inv + b);
    }
}

// ================= fp16 mma GEMM 128x128, BK=64, 3 stages, 2 CTAs/SM =================
#define ATILE_B 16384
#define STAGE_B 32768
#define GEMM_SMEM (3 * STAGE_B)   // 96 KB

template<int EPI>
__global__ void __launch_bounds__(256, 2)
gemm_h(const __half* __restrict__ A, const __half* __restrict__ Bt,
       const float* __restrict__ bias, const float* __restrict__ res,
       void* __restrict__ C0v, void* __restrict__ C1v, void* __restrict__ C2v,
       int M, int N, int K) {
    extern __shared__ char smem[];
    uint32_t sb = smem_u32(smem);
    int tid = threadIdx.x;
    int lane = tid & 31, wid = tid >> 5;
    int wm = wid >> 2, wn = wid & 3;
    int g = lane >> 2, tig = lane & 3;
    int m0 = blockIdx.y * 128, n0 = blockIdx.x * 128;
    const __half* Ab = A  + (size_t)m0 * K;
    const __half* Bb = Bt + (size_t)n0 * K;
    const int NT = K / 64;

    const uint32_t rlA = (uint32_t)(wm * 64 + (lane & 15));
    const uint32_t klA = (uint32_t)(lane >> 4);
    const uint32_t rlB = (uint32_t)(wn * 32 + ((lane >> 4) << 3) + (lane & 7));
    const uint32_t klB = (uint32_t)((lane >> 3) & 1);

    float acc[4][4][4];
    #pragma unroll
    for (int i = 0; i < 4; i++)
        #pragma unroll
        for (int j = 0; j < 4; j++)
            #pragma unroll
            for (int r = 0; r < 4; r++) acc[i][j][r] = 0.f;

    auto LOAD = [&](int t) {
        int s = t % 3;
        uint32_t ab = sb + s * STAGE_B;
        uint32_t bb = ab + ATILE_B;
        int kt = t * 64;
        #pragma unroll
        for (int u = 0; u < 4; u++) {
            int idx = tid + u * 256;
            int r = idx >> 3, c = idx & 7;
            uint32_t sw = (uint32_t)r * 128 + (uint32_t)((c ^ (r & 7)) << 4);
            CP_ASYNC16(ab + sw, Ab + (size_t)r * K + kt + c * 8);
            CP_ASYNC16(bb + sw, Bb + (size_t)r * K + kt + c * 8);
        }
        CP_COMMIT();
    };

    LOAD(0); LOAD(1);

    for (int t = 0; t < NT; t++) {
        if (t + 2 < NT) { CP_WAIT(1); } else { CP_WAIT(0); }
        __syncthreads();
        if (t + 2 < NT) LOAD(t + 2);

        int s = t % 3;
        uint32_t ab = sb + s * STAGE_B;
        uint32_t bb = ab + ATILE_B;

        #pragma unroll
        for (int ks = 0; ks < 4; ks++) {
            uint32_t afr[4][4], bfr[4][2];
            #pragma unroll
            for (int mi = 0; mi < 4; mi++) {
                uint32_t rl = rlA + (uint32_t)(mi * 16);
                uint32_t cl = (uint32_t)(2 * ks) | klA;
                ldsm4(afr[mi], ab + rl * 128 + ((cl ^ (rl & 7)) << 4));
            }
            #pragma unroll
            for (int j = 0; j < 2; j++) {
                uint32_t rl = rlB + (uint32_t)(j * 16);
                uint32_t cl = (uint32_t)(2 * ks) | klB;
                uint32_t tmp[4];
                ldsm4(tmp, bb + rl * 128 + ((cl ^ (rl & 7)) << 4));
                bfr[2*j][0]   = tmp[0]; bfr[2*j][1]   = tmp[1];
                bfr[2*j+1][0] = tmp[2]; bfr[2*j+1][1] = tmp[3];
            }
            #pragma unroll
            for (int mi = 0; mi < 4; mi++)
                #pragma unroll
                for (int nj = 0; nj < 4; nj++)
                    mma16h(acc[mi][nj], afr[mi], bfr[nj]);
        }
    }

    // ---- staged V-transpose path (QKV tiles with n0 >= 1536) ----
    if (EPI == 1 && n0 >= 1536) {
        __syncthreads();
        __half* T = (__half*)smem;   // [128][136] halfs
        #pragma unroll
        for (int mi = 0; mi < 4; mi++) {
            #pragma unroll
            for (int nj = 0; nj < 4; nj++) {
                int ml = wm * 64 + mi * 16 + g;
                int nl = wn * 32 + nj * 8 + tig * 2;
                int n = n0 + nl;
                float b0 = bias[n], b1 = bias[n + 1];
                T[nl * 136 + ml]           = __float2half(acc[mi][nj][0] + b0);
                T[(nl + 1) * 136 + ml]     = __float2half(acc[mi][nj][1] + b1);
                T[nl * 136 + ml + 8]       = __float2half(acc[mi][nj][2] + b0);
                T[(nl + 1) * 136 + ml + 8] = __float2half(acc[mi][nj][3] + b1);
            }
        }
        __syncthreads();
        int b_ = m0 >> 11, s_ = m0 & (SEQ - 1);
        int nbase = n0 - 1536;
        __half* vt = (__half*)C2v;
        #pragma unroll
        for (int u = 0; u < 8; u++) {
            int idx = tid + u * 256;
            int r = idx >> 4, ch = idx & 15;
            int ng = nbase + r;
            int h = ng >> 6, d = ng & 63;
            uint4 val = *(uint4*)&T[r * 136 + ch * 8];
            *(uint4*)&vt[(((size_t)(b_ * NH + h) * DK + d) * SEQ + s_ + ch * 8)] = val;
        }
        return;
    }

    #pragma unroll
    for (int mi = 0; mi < 4; mi++) {
        #pragma unroll
        for (int nj = 0; nj < 4; nj++) {
            int m = m0 + wm * 64 + mi * 16 + g;
            int n = n0 + wn * 32 + nj * 8 + tig * 2;
            float b0 = bias[n], b1 = bias[n + 1];
            float v0 = acc[mi][nj][0] + b0, v1 = acc[mi][nj][1] + b1;
            float v2 = acc[mi][nj][2] + b0, v3 = acc[mi][nj][3] + b1;
            if (EPI == 1) {
                int isq = (n < 768);
                int nn = isq ? n : (n - 768);
                int h = nn >> 6, d = nn & 63;
                int b_ = m >> 11, s_ = m & (SEQ - 1);
                __half* dst = isq ? (__half*)C0v : (__half*)C1v;
                size_t base = (((size_t)(b_ * NH + h) * SEQ + s_) << 6) + d;
                *(__half2*)&dst[base] = __floats2half2_rn(v0, v1);
                size_t base2 = (((size_t)(b_ * NH + h) * SEQ + (s_ + 8)) << 6) + d;
                *(__half2*)&dst[base2] = __floats2half2_rn(v2, v3);
            } else {
                __half* C0 = (__half*)C0v;
                *(__half2*)&C0[(size_t)m * N + n] =
                    __floats2half2_rn(fmaxf(v0, 0.f), fmaxf(v1, 0.f));
                *(__half2*)&C0[(size_t)(m + 8) * N + n] =
                    __floats2half2_rn(fmaxf(v2, 0.f), fmaxf(v3, 0.f));
            }
        }
    }
}

// ==== fp16 mma GEMM 64x128, BK=64, 3 stages, 256 thr (8 warps 2x4), 3 CTAs/SM ====
#define ATILE64_B 8192
#define STAGE64_B 24576
#define GEMM64_SMEM (3 * STAGE64_B)   // 72 KB

__global__ void __launch_bounds__(256, 3)
gemm_h64(const __half* __restrict__ A, const __half* __restrict__ Bt,
         const float* __restrict__ bias, const float* __restrict__ res,
         float* __restrict__ C0, int M, int N, int K) {
    extern __shared__ char smem[];
    uint32_t sb = smem_u32(smem);
    int tid = threadIdx.x;
    int lane = tid & 31, wid = tid >> 5;
    int wm = wid >> 2, wn = wid & 3;          // 2(m) x 4(n), warp tile 32x32
    int g = lane >> 2, tig = lane & 3;
    int m0 = blockIdx.y * 64, n0 = blockIdx.x * 128;
    const __half* Ab = A  + (size_t)m0 * K;
    const __half* Bb = Bt + (size_t)n0 * K;
    const int NT = K / 64;

    const uint32_t rlA = (uint32_t)(wm * 32 + (lane & 15));
    const uint32_t klA = (uint32_t)(lane >> 4);
    const uint32_t rlB = (uint32_t)(wn * 32 + ((lane >> 4) << 3) + (lane & 7));
    const uint32_t klB = (uint32_t)((lane >> 3) & 1);

    float acc[2][4][4];
    #pragma unroll
    for (int i = 0; i < 2; i++)
        #pragma unroll
        for (int j = 0; j < 4; j++)
            #pragma unroll
            for (int r = 0; r < 4; r++) acc[i][j][r] = 0.f;

    auto LOAD = [&](int t) {
        int s = t % 3;
        uint32_t ab = sb + s * STAGE64_B;
        uint32_t bb = ab + ATILE64_B;
        int kt = t * 64;
        // A: 64 rows x 8 chunks = 512 / 256 thr = 2 iters
        #pragma unroll
        for (int u = 0; u < 2; u++) {
            int idx = tid + u * 256;
            int r = idx >> 3, c = idx & 7;
            uint32_t sw = (uint32_t)r * 128 + (uint32_t)((c ^ (r & 7)) << 4);
            CP_ASYNC16(ab + sw, Ab + (size_t)r * K + kt + c * 8);
        }
        // B: 128 rows x 8 chunks = 1024 / 256 thr = 4 iters
        #pragma unroll
        for (int u = 0; u < 4; u++) {
            int idx = tid + u * 256;
            int r = idx >> 3, c = idx & 7;
            uint32_t sw = (uint32_t)r * 128 + (uint32_t)((c ^ (r & 7)) << 4);
            CP_ASYNC16(bb + sw, Bb + (size_t)r * K + kt + c * 8);
        }
        CP_COMMIT();
    };

    LOAD(0); LOAD(1);

    for (int t = 0; t < NT; t++) {
        if (t + 2 < NT) { CP_WAIT(1); } else { CP_WAIT(0); }
        __syncthreads();
        if (t + 2 < NT) LOAD(t + 2);

        int s = t % 3;
        uint32_t ab = sb + s * STAGE64_B;
        uint32_t bb = ab + ATILE64_B;

        #pragma unroll
        for (int ks = 0; ks < 4; ks++) {
            uint32_t afr[2][4], bfr[4][2];
            #pragma unroll
            for (int mi = 0; mi < 2; mi++) {
                uint32_t rl = rlA + (uint32_t)(mi * 16);
                uint32_t cl = (uint32_t)(2 * ks) | klA;
                ldsm4(afr[mi], ab + rl * 128 + ((cl ^ (rl & 7)) << 4));
            }
            #pragma unroll
            for (int j = 0; j < 2; j++) {
                uint32_t rl = rlB + (uint32_t)(j * 16);
                uint32_t cl = (uint32_t)(2 * ks) | klB;
                uint32_t tmp[4];
                ldsm4(tmp, bb + rl * 128 + ((cl ^ (rl & 7)) << 4));
                bfr[2*j][0]   = tmp[0]; bfr[2*j][1]   = tmp[1];
                bfr[2*j+1][0] = tmp[2]; bfr[2*j+1][1] = tmp[3];
            }
            #pragma unroll
            for (int mi = 0; mi < 2; mi++)
                #pragma unroll
                for (int nj = 0; nj < 4; nj++)
                    mma16h(acc[mi][nj], afr[mi], bfr[nj]);
        }
    }

    #pragma unroll
    for (int mi = 0; mi < 2; mi++) {
        #pragma unroll
        for (int nj = 0; nj < 4; nj++) {
            int m = m0 + wm * 32 + mi * 16 + g;
            int n = n0 + wn * 32 + nj * 8 + tig * 2;
            float b0 = bias[n], b1 = bias[n + 1];
            float v0 = acc[mi][nj][0] + b0, v1 = acc[mi][nj][1] + b1;
            float v2 = acc[mi][nj][2] + b0, v3 = acc[mi][nj][3] + b1;
            float2 r0 = *(const float2*)&res[(size_t)m * N + n];
            float2 r1 = *(const float2*)&res[(size_t)(m + 8) * N + n];
            *(float2*)&C0[(size_t)m * N + n] = make_float2(v0 + r0.x, v1 + r0.y);
            *(float2*)&C0[(size_t)(m + 8) * N + n] = make_float2(v2 + r1.x, v3 + r1.y);
        }
    }
}

// ================= Flash attention: BQ=64, fast base-2 softmax, deferred l ==========
#define ATT_SMEM 40960

__global__ void __launch_bounds__(128, 3)
attn_h(const __half* __restrict__ Q, const __half* __restrict__ K,
       const __half* __restrict__ Vt, const int* __restrict__ mask,
       const int* __restrict__ mflag, __half* __restrict__ ctx) {
    extern __shared__ char sm[];
    uint32_t sb = smem_u32(sm);
    const uint32_t qs = sb;
    const uint32_t ks = sb + 8192;
    const uint32_t vs = sb + 24576;

    int tid = threadIdx.x;
    int lane = tid & 31, wr = tid >> 5;
    int g = lane >> 2, tig = lane & 3;
    int bh = blockIdx.y;
    int q0 = blockIdx.x * 64;
    const __half* Qb = Q  + (size_t)bh * SEQ * DK + (size_t)q0 * DK;
    const __half* Kb = K  + (size_t)bh * SEQ * DK;
    const __half* Vb = Vt + (size_t)bh * DK * SEQ;
    const int* flags = mflag + (blockIdx.x >> 1) * (SEQ / 64);

    const uint32_t rlQ = (uint32_t)(wr * 16 + (lane & 15));
    const uint32_t klQ = (uint32_t)(lane >> 4);
    const uint32_t rlB = (uint32_t)(((lane >> 4) << 3) + (lane & 7));
    const uint32_t klB = (uint32_t)((lane >> 3) & 1);

    #pragma unroll
    for (int u = 0; u < 4; u++) {
        int idx = tid + u * 128;
        int r = idx >> 3, c = idx & 7;
        uint32_t sw = (uint32_t)r * 128 + (uint32_t)((c ^ (r & 7)) * 16);
        CP_ASYNC16(qs + sw, Qb + (size_t)r * DK + c * 8);
    }
    auto LOADKV = [&](int buf, int t) {
        int k0 = t * 64;
        uint32_t kb = ks + (uint32_t)buf * 8192;
        uint32_t vb = vs + (uint32_t)buf * 8192;
        #pragma unroll
        for (int u = 0; u < 4; u++) {
            int idx = tid + u * 128;
            int r = idx >> 3, c = idx & 7;
            uint32_t sw = (uint32_t)r * 128 + (uint32_t)((c ^ (r & 7)) * 16);
            CP_ASYNC16(kb + sw, Kb + (size_t)(k0 + r) * DK + c * 8);
            CP_ASYNC16(vb + sw, Vb + (size_t)r * SEQ + k0 + c * 8);
        }
        CP_COMMIT();
    };
    LOADKV(0, 0);
    CP_WAIT(0);
    __syncthreads();

    uint32_t qfr[4][4];
    #pragma unroll
    for (int kc = 0; kc < 4; kc++) {
        uint32_t cl = (uint32_t)(2 * kc) | klQ;
        ldsm4(qfr[kc], qs + rlQ * 128 + ((cl ^ (rlQ & 7)) << 4));
    }

    float l0 = 0.f, l1 = 0.f;
    float o[8][4];
    #pragma unroll
    for (int j = 0; j < 8; j++)
        #pragma unroll
        for (int r = 0; r < 4; r++) o[j][r] = 0.f;

    const int row0 = wr * 16 + g;
    const int NT = SEQ / 64;

    for (int kt = 0; kt < NT; kt++) {
        if (kt + 1 < NT) LOADKV((kt + 1) & 1, kt + 1);

        int buf = kt & 1;
        uint32_t kbase = ks + (uint32_t)buf * 8192;
        uint32_t vbase = vs + (uint32_t)buf * 8192;

        float sacc[8][4];
        #pragma unroll
        for (int j = 0; j < 8; j++)
            #pragma unroll
            for (int r = 0; r < 4; r++) sacc[j][r] = 0.f;
        #pragma unroll
        for (int kc = 0; kc < 4; kc++) {
            uint32_t cl = (uint32_t)(2 * kc) | klB;
            #pragma unroll
            for (int j = 0; j < 4; j++) {
                uint32_t rl = rlB + (uint32_t)(j * 16);
                uint32_t tmp[4];
                ldsm4(tmp, kbase + rl * 128 + ((cl ^ (rl & 7)) << 4));
                uint32_t b0[2] = {tmp[0], tmp[1]}, b1[2] = {tmp[2], tmp[3]};
                mma16h(sacc[2*j],   qfr[kc], b0);
                mma16h(sacc[2*j+1], qfr[kc], b1);
            }
        }

        if (flags[kt]) {
            #pragma unroll
            for (int nj = 0; nj < 8; nj++) {
                float p0 = fexp2m(fmaf(sacc[nj][0], EXP_C1, EXP_C0));
                float p1 = fexp2m(fmaf(sacc[nj][1], EXP_C1, EXP_C0));
                float p2 = fexp2m(fmaf(sacc[nj][2], EXP_C1, EXP_C0));
                float p3 = fexp2m(fmaf(sacc[nj][3], EXP_C1, EXP_C0));
                l0 += p0 + p1; l1 += p2 + p3;
                sacc[nj][0] = p0; sacc[nj][1] = p1;
                sacc[nj][2] = p2; sacc[nj][3] = p3;
            }
        } else {
            int kg0 = kt * 64;
            const int* mr0 = mask + (size_t)(q0 + row0) * SEQ + kg0;
            const int* mr1 = mr0 + (size_t)8 * SEQ;
            #pragma unroll
            for (int nj = 0; nj < 8; nj++) {
                int c = nj * 8 + 2 * tig;
                int2 mk0 = *(const int2*)&mr0[c];
                int2 mk1 = *(const int2*)&mr1[c];
                float y0 = fmaxf(fmaf(sacc[nj][0], EXP_C1, EXP_C0), -126.f);
                float y1 = fmaxf(fmaf(sacc[nj][1], EXP_C1, EXP_C0), -126.f);
                float y2 = fmaxf(fmaf(sacc[nj][2], EXP_C1, EXP_C0), -126.f);
                float y3 = fmaxf(fmaf(sacc[nj][3], EXP_C1, EXP_C0), -126.f);
                float p0 = (mk0.x == 0) ? 0.f : fexp2m(y0);
                float p1 = (mk0.y == 0) ? 0.f : fexp2m(y1);
                float p2 = (mk1.x == 0) ? 0.f : fexp2m(y2);
                float p3 = (mk1.y == 0) ? 0.f : fexp2m(y3);
                l0 += p0 + p1; l1 += p2 + p3;
                sacc[nj][0] = p0; sacc[nj][1] = p1;
                sacc[nj][2] = p2; sacc[nj][3] = p3;
            }
        }

        #pragma unroll
        for (int kc = 0; kc < 4; kc++) {
            uint32_t afr[4];
            afr[0] = packh2(sacc[2*kc][0],   sacc[2*kc][1]);
            afr[1] = packh2(sacc[2*kc][2],   sacc[2*kc][3]);
            afr[2] = packh2(sacc[2*kc+1][0], sacc[2*kc+1][1]);
            afr[3] = packh2(sacc[2*kc+1][2], sacc[2*kc+1][3]);
            uint32_t cl = (uint32_t)(2 * kc) | klB;
            #pragma unroll
            for (int j = 0; j < 4; j++) {
                uint32_t rl = rlB + (uint32_t)(j * 16);
                uint32_t tmp[4];
                ldsm4(tmp, vbase + rl * 128 + ((cl ^ (rl & 7)) << 4));
                uint32_t b0[2] = {tmp[0], tmp[1]}, b1[2] = {tmp[2], tmp[3]};
                mma16h(o[2*j],   afr, b0);
                mma16h(o[2*j+1], afr, b1);
            }
        }

        if (kt + 1 < NT) { CP_WAIT(0); __syncthreads(); }
    }

    l0 += __shfl_xor_sync(0xffffffffu, l0, 1);
    l0 += __shfl_xor_sync(0xffffffffu, l0, 2);
    l1 += __shfl_xor_sync(0xffffffffu, l1, 1);
    l1 += __shfl_xor_sync(0xffffffffu, l1, 2);

    float inv0 = 1.f / l0, inv1 = 1.f / l1;
    int b_ = bh / NH, h_ = bh % NH;
    __half* base0 = ctx + (size_t)(b_ * SEQ + q0 + row0) * DM + h_ * 64;
    __half* base1 = base0 + (size_t)8 * DM;
    #pragma unroll
    for (int nj = 0; nj < 8; nj++) {
        int c = nj * 8 + 2 * tig;
        *(__half2*)&base0[c] = __floats2half2_rn(o[nj][0] * inv0, o[nj][1] * inv0);
        *(__half2*)&base1[c] = __floats2half2_rn(o[nj][2] * inv1, o[nj][3] * inv1);
    }
}

// ---------------- launch ----------------
extern "C" void kernel_launch(void* const* d_in, const int* in_sizes, int n_in,
                              void* d_out, int out_size) {
    (void)in_sizes; (void)n_in; (void)out_size;
    const float* x    = (const float*)d_in[0];
    const int*   mask = (const int*)  d_in[1];
    const float* wq = (const float*)d_in[2];
    const float* bq = (const float*)d_in[3];
    const float* wk = (const float*)d_in[4];
    const float* bk = (const float*)d_in[5];
    const float* wv = (const float*)d_in[6];
    const float* bv = (const float*)d_in[7];
    const float* wo = (const float*)d_in[8];
    const float* bo = (const float*)d_in[9];
    const float* w1 = (const float*)d_in[10];
    const float* b1 = (const float*)d_in[11];
    const float* w2 = (const float*)d_in[12];
    const float* b2 = (const float*)d_in[13];
    const float* alpha1 = (const float*)d_in[14];
    const float* beta1  = (const float*)d_in[15];
    const float* alpha2 = (const float*)d_in[16];
    const float* beta2  = (const float*)d_in[17];
    float* out = (float*)d_out;

    __half *xnh, *qh, *kh, *vth, *ctxh, *ffh, *wth;
    float *x1, *bqkv;
    int* mflag;
    cudaGetSymbolAddress((void**)&xnh,  g_xnh);
    cudaGetSymbolAddress((void**)&qh,   g_qh);
    cudaGetSymbolAddress((void**)&kh,   g_kh);
    cudaGetSymbolAddress((void**)&vth,  g_vth);
    cudaGetSymbolAddress((void**)&ctxh, g_ctxh);
    cudaGetSymbolAddress((void**)&x1,   g_x1);
    cudaGetSymbolAddress((void**)&ffh,  g_ffh);
    cudaGetSymbolAddress((void**)&wth,  g_wth);
    cudaGetSymbolAddress((void**)&bqkv, g_bqkv);
    cudaGetSymbolAddress((void**)&mflag, g_mflag);

    cudaFuncSetAttribute(attn_h, cudaFuncAttributeMaxDynamicSharedMemorySize, ATT_SMEM);
    cudaFuncSetAttribute(gemm_h<1>, cudaFuncAttributeMaxDynamicSharedMemorySize, GEMM_SMEM);
    cudaFuncSetAttribute(gemm_h<3>, cudaFuncAttributeMaxDynamicSharedMemorySize, GEMM_SMEM);
    cudaFuncSetAttribute(gemm_h64, cudaFuncAttributeMaxDynamicSharedMemorySize, GEMM64_SMEM);

    prep_all<<<PREP_BLOCKS, 256>>>(x, alpha1, beta1, mask,                 // 1
        wq, wk, wv, wo, w1, w2, bq, bk, bv, wth, bqkv, mflag, xnh);

    gemm_h<1><<<dim3(2304/128, ROWS/128), 256, GEMM_SMEM>>>(               // 2
        xnh, wth + WT_QKV, bqkv, nullptr, qh, kh, vth, ROWS, 2304, DM);

    attn_h<<<dim3(SEQ/64, BS_ * NH), 128, ATT_SMEM>>>(                     // 3
        qh, kh, vth, mask, mflag, ctxh);

    gemm_h64<<<dim3(DM/128, ROWS/64), 256, GEMM64_SMEM>>>(                 // 4
        ctxh, wth + WT_O, bo, x, x1, ROWS, DM, DM);

    ln_kernel<<<ROWS, 256>>>(x1, alpha2, beta2, xnh);                      // 5

    gemm_h<3><<<dim3(FF/128, ROWS/128), 256, GEMM_SMEM>>>(                 // 6
        xnh, wth + WT_1, b1, nullptr, ffh, nullptr, nullptr, ROWS, FF, DM);

    gemm_h64<<<dim3(DM/128, ROWS/64), 256, GEMM64_SMEM>>>(                 // 7
        ffh, wth + WT_2, b2, x1, out, ROWS, DM, FF);
}

// round 17
// speedup vs baseline: 1.0142x; 1.0142x over previous
#include <cuda_runtime.h>
#include <cuda_fp16.h>
#include <math.h>
#include <math_constants.h>
#include <stdint.h>

#define BS_  2
#define SEQ  2048
#define DM   768
#define FF   3072
#define NH   12
#define DK   64
#define ROWS (BS_*SEQ)   // 4096

// ---------------- scratch (allocation-free: device globals) ----------------
__device__ __half g_xnh [ROWS*(size_t)DM];
__device__ __half g_qh  [ROWS*(size_t)DM];     // [B,H,S,dk]
__device__ __half g_kh  [ROWS*(size_t)DM];     // [B,H,S,dk]
__device__ __half g_vth [ROWS*(size_t)DM];     // [B,H,dk,S] (transposed V)
__device__ __half g_ctxh[ROWS*(size_t)DM];
__device__ float  g_x1 [ROWS*(size_t)DM];
__device__ __half g_ffh [ROWS*(size_t)FF];
#define WT_QKV 0
#define WT_O   (2304*768)
#define WT_1   (WT_O + 768*768)
#define WT_2   (WT_1 + 3072*768)
__device__ __half g_wth [WT_2 + (size_t)768*3072];
__device__ float  g_bqkv[2304];
__device__ int    g_mflag[(SEQ/128)*(SEQ/64)];

// ================= helpers =================
__device__ __forceinline__ uint32_t smem_u32(const void* p) {
    uint32_t a;
    asm("{ .reg .u64 t; cvta.to.shared.u64 t, %1; cvt.u32.u64 %0, t; }" : "=r"(a) : "l"(p));
    return a;
}
__device__ __forceinline__ void ldsm4(uint32_t* r, uint32_t addr) {
    asm volatile("ldmatrix.sync.aligned.m8n8.x4.shared.b16 {%0,%1,%2,%3}, [%4];"
        : "=r"(r[0]), "=r"(r[1]), "=r"(r[2]), "=r"(r[3]) : "r"(addr));
}
__device__ __forceinline__ uint32_t packh2(float a, float b) {
    __half2 h = __floats2half2_rn(a, b);
    return *(uint32_t*)&h;
}
__device__ __forceinline__ void mma16h(float* d, const uint32_t* a, const uint32_t* b) {
    asm volatile(
        "mma.sync.aligned.m16n8k16.row.col.f32.f16.f16.f32 "
        "{%0,%1,%2,%3}, {%4,%5,%6,%7}, {%8,%9}, {%0,%1,%2,%3};"
        : "+f"(d[0]), "+f"(d[1]), "+f"(d[2]), "+f"(d[3])
        : "r"(a[0]), "r"(a[1]), "r"(a[2]), "r"(a[3]), "r"(b[0]), "r"(b[1]));
}
#define CP_ASYNC16(dst, src) \
    asm volatile("cp.async.cg.shared.global [%0], [%1], 16;" :: "r"(dst), "l"(src))
#define CP_COMMIT() asm volatile("cp.async.commit_group;" ::: "memory")
#define CP_WAIT(n)  asm volatile("cp.async.wait_group %0;" :: "n"(n) : "memory")

// fast 2^y via magic-number round-to-nearest
#define EXP2_KINT (0x4B400000 - (127 << 0))
__device__ __forceinline__ float fexp2m(float y) {
    float t = y + 12582912.f;                 // 1.5 * 2^23
    float r = y - (t - 12582912.f);
    float sc = __int_as_float((__float_as_int(t) - EXP2_KINT) << 23);
    float p = 1.3333558146428443e-3f;
    p = fmaf(p, r, 9.6181291076284772e-3f);
    p = fmaf(p, r, 5.5504108664821580e-2f);
    p = fmaf(p, r, 2.4022650695910071e-1f);
    p = fmaf(p, r, 6.9314718055994531e-1f);
    p = fmaf(p, r, 1.0f);
    return p * sc;
}
#define EXP_C1 0.18033688011112042f
#define EXP_C0 (-11.541560327111707f)

// ================= merged prep: transposes + bias + mask flags + LN1 =================
#define PREP_BLOCKS 11523

__global__ void prep_all(const float* __restrict__ x,
                         const float* __restrict__ alpha1, const float* __restrict__ beta1,
                         const int* __restrict__ mask,
                         const float* __restrict__ wq, const float* __restrict__ wk,
                         const float* __restrict__ wv, const float* __restrict__ wo,
                         const float* __restrict__ w1, const float* __restrict__ w2,
                         const float* __restrict__ bq, const float* __restrict__ bk,
                         const float* __restrict__ bv,
                         __half* __restrict__ wt, float* __restrict__ bqkv,
                         int* __restrict__ flags, __half* __restrict__ xn) {
    __shared__ float sh[32 * 33];
    int bid = blockIdx.x;
    int tid = threadIdx.x;

    if (bid < 6912) {
        int tx = tid & 31, ty = tid >> 5;
        const float* src; __half* dst; int K, N, bx, by;
        if (bid < 2304) {
            int j = bid / 576, loc = bid % 576;
            bx = loc % 24; by = loc / 24; K = 768; N = 768;
            src = (j == 0) ? wq : (j == 1) ? wk : (j == 2) ? wv : wo;
            dst = wt + ((j == 3) ? WT_O : WT_QKV + j * 768 * 768);
        } else if (bid < 4608) {
            int loc = bid - 2304;
            bx = loc % 96; by = loc / 96; K = 768; N = 3072;
            src = w1; dst = wt + WT_1;
        } else {
            int loc = bid - 4608;
            bx = loc % 24; by = loc / 24; K = 3072; N = 768;
            src = w2; dst = wt + WT_2;
        }
        int n0 = bx * 32, k0 = by * 32;
        #pragma unroll
        for (int i = 0; i < 32; i += 8)
            sh[(ty + i) * 33 + tx] =
                src[(size_t)(k0 + ty + i) * N + n0 + tx];
        __syncthreads();
        #pragma unroll
        for (int i = 0; i < 32; i += 8)
            dst[(size_t)(n0 + ty + i) * K + k0 + tx] =
                __float2half(sh[tx * 33 + ty + i]);
    } else if (bid < 6915) {
        int i = (bid - 6912) * 256 + tid;
        if (i < 768) { bqkv[i] = bq[i]; bqkv[768 + i] = bk[i]; bqkv[1536 + i] = bv[i]; }
    } else if (bid < 7427) {
        int mb = bid - 6915;
        int qt = mb >> 5, kt = mb & 31;
        const int* mr = mask + (size_t)(qt * 128 + (tid >> 1)) * SEQ + kt * 64 + (tid & 1) * 32;
        int all = 1;
        #pragma unroll
        for (int i = 0; i < 8; i++) {
            int4 m = *(const int4*)&mr[i * 4];
            all &= (m.x != 0) & (m.y != 0) & (m.z != 0) & (m.w != 0);
        }
        all = __syncthreads_and(all);
        if (tid == 0) flags[mb] = all;
    } else {
        int row = bid - 7427;
        const float* xr = x + (size_t)row * DM;
        float s = 0.f, s2 = 0.f;
        for (int i = tid; i < DM; i += 256) {
            float v = xr[i]; s += v; s2 += v * v;
        }
        #pragma unroll
        for (int o = 16; o; o >>= 1) {
            s  += __shfl_down_sync(0xffffffffu, s,  o);
            s2 += __shfl_down_sync(0xffffffffu, s2, o);
        }
        int w = tid >> 5, l = tid & 31;
        if (l == 0) { sh[w] = s; sh[32 + w] = s2; }
        __syncthreads();
        if (tid == 0) {
            float S = 0.f, S2 = 0.f;
            for (int i = 0; i < 8; i++) { S += sh[i]; S2 += sh[32 + i]; }
            float mean = S / DM;
            float var  = (S2 - DM * mean * mean) / (DM - 1);
            sh[0] = mean;
            sh[1] = rsqrtf(var + 1e-6f);
        }
        __syncthreads();
        float mean = sh[0], inv = sh[1];
        float a = alpha1[0], b = beta1[0];
        __half2* yr = (__half2*)(xn + (size_t)row * DM);
        const float2* xr2 = (const float2*)xr;
        for (int i = tid; i < DM / 2; i += 256) {
            float2 v = xr2[i];
            yr[i] = __floats2half2_rn(a * (v.x - mean) * inv + b,
                                      a * (v.y - mean) * inv + b);
        }
    }
}

// ---------------- LayerNorm (ddof=1) -> fp16 (LN2) ----------------
__global__ void ln_kernel(const float* __restrict__ x,
                          const float* __restrict__ alpha,
                          const float* __restrict__ beta,
                          __half* __restrict__ y) {
    int row = blockIdx.x;
    const float* xr = x + (size_t)row * DM;
    float s = 0.f, s2 = 0.f;
    for (int i = threadIdx.x; i < DM; i += blockDim.x) {
        float v = xr[i]; s += v; s2 += v * v;
    }
    __shared__ float red[64];
    #pragma unroll
    for (int o = 16; o; o >>= 1) {
        s  += __shfl_down_sync(0xffffffffu, s,  o);
        s2 += __shfl_down_sync(0xffffffffu, s2, o);
    }
    int w = threadIdx.x >> 5, l = threadIdx.x & 31;
    if (l == 0) { red[w] = s; red[32 + w] = s2; }
    __syncthreads();
    if (threadIdx.x == 0) {
        float S = 0.f, S2 = 0.f;
        int nw = blockDim.x >> 5;
        for (int i = 0; i < nw; i++) { S += red[i]; S2 += red[32 + i]; }
        float mean = S / DM;
        float var  = (S2 - DM * mean * mean) / (DM - 1);
        red[0] = mean;
        red[1] = rsqrtf(var + 1e-6f);
    }
    __syncthreads();
    float mean = red[0], inv = red[1];
    float a = alpha[0], b = beta[0];
    __half2* yr = (__half2*)(y + (size_t)row * DM);
    const float2* xr2 = (const float2*)xr;
    for (int i = threadIdx.x; i < DM / 2; i += blockDim.x) {
        float2 v = xr2[i];
        yr[i] = __floats2half2_rn(a * (v.x - mean) * inv + b,
                                  a * (v.y - mean) * inv + b);
    }
}

// ================= fp16 mma GEMM 128x128, BK=64, 3 stages, 2 CTAs/SM =================
#define ATILE_B 16384
#define STAGE_B 32768
#define GEMM_SMEM (3 * STAGE_B)   // 96 KB

template<int EPI>
__global__ void __launch_bounds__(256, 2)
gemm_h(const __half* __restrict__ A, const __half* __restrict__ Bt,
       const float* __restrict__ bias, const float* __restrict__ res,
       void* __restrict__ C0v, void* __restrict__ C1v, void* __restrict__ C2v,
       int M, int N, int K) {
    extern __shared__ char smem[];
    uint32_t sb = smem_u32(smem);
    int tid = threadIdx.x;
    int lane = tid & 31, wid = tid >> 5;
    int wm = wid >> 2, wn = wid & 3;
    int g = lane >> 2, tig = lane & 3;
    int m0 = blockIdx.y * 128, n0 = blockIdx.x * 128;
    const __half* Ab = A  + (size_t)m0 * K;
    const __half* Bb = Bt + (size_t)n0 * K;
    const int NT = K / 64;

    const uint32_t rlA = (uint32_t)(wm * 64 + (lane & 15));
    const uint32_t klA = (uint32_t)(lane >> 4);
    const uint32_t rlB = (uint32_t)(wn * 32 + ((lane >> 4) << 3) + (lane & 7));
    const uint32_t klB = (uint32_t)((lane >> 3) & 1);

    float acc[4][4][4];
    #pragma unroll
    for (int i = 0; i < 4; i++)
        #pragma unroll
        for (int j = 0; j < 4; j++)
            #pragma unroll
            for (int r = 0; r < 4; r++) acc[i][j][r] = 0.f;

    auto LOAD = [&](int t) {
        int s = t % 3;
        uint32_t ab = sb + s * STAGE_B;
        uint32_t bb = ab + ATILE_B;
        int kt = t * 64;
        #pragma unroll
        for (int u = 0; u < 4; u++) {
            int idx = tid + u * 256;
            int r = idx >> 3, c = idx & 7;
            uint32_t sw = (uint32_t)r * 128 + (uint32_t)((c ^ (r & 7)) << 4);
            CP_ASYNC16(ab + sw, Ab + (size_t)r * K + kt + c * 8);
            CP_ASYNC16(bb + sw, Bb + (size_t)r * K + kt + c * 8);
        }
        CP_COMMIT();
    };

    LOAD(0); LOAD(1);

    for (int t = 0; t < NT; t++) {
        if (t + 2 < NT) { CP_WAIT(1); } else { CP_WAIT(0); }
        __syncthreads();
        if (t + 2 < NT) LOAD(t + 2);

        int s = t % 3;
        uint32_t ab = sb + s * STAGE_B;
        uint32_t bb = ab + ATILE_B;

        #pragma unroll
        for (int ks = 0; ks < 4; ks++) {
            uint32_t afr[4][4], bfr[4][2];
            #pragma unroll
            for (int mi = 0; mi < 4; mi++) {
                uint32_t rl = rlA + (uint32_t)(mi * 16);
                uint32_t cl = (uint32_t)(2 * ks) | klA;
                ldsm4(afr[mi], ab + rl * 128 + ((cl ^ (rl & 7)) << 4));
            }
            #pragma unroll
            for (int j = 0; j < 2; j++) {
                uint32_t rl = rlB + (uint32_t)(j * 16);
                uint32_t cl = (uint32_t)(2 * ks) | klB;
                uint32_t tmp[4];
                ldsm4(tmp, bb + rl * 128 + ((cl ^ (rl & 7)) << 4));
                bfr[2*j][0]   = tmp[0]; bfr[2*j][1]   = tmp[1];
                bfr[2*j+1][0] = tmp[2]; bfr[2*j+1][1] = tmp[3];
            }
            #pragma unroll
            for (int mi = 0; mi < 4; mi++)
                #pragma unroll
                for (int nj = 0; nj < 4; nj++)
                    mma16h(acc[mi][nj], afr[mi], bfr[nj]);
        }
    }

    // ---- staged V-transpose path (QKV tiles with n0 >= 1536) ----
    if (EPI == 1 && n0 >= 1536) {
        __syncthreads();
        __half* T = (__half*)smem;   // [128][136] halfs
        #pragma unroll
        for (int mi = 0; mi < 4; mi++) {
            #pragma unroll
            for (int nj = 0; nj < 4; nj++) {
                int ml = wm * 64 + mi * 16 + g;
                int nl = wn * 32 + nj * 8 + tig * 2;
                int n = n0 + nl;
                float b0 = bias[n], b1 = bias[n + 1];
                T[nl * 136 + ml]           = __float2half(acc[mi][nj][0] + b0);
                T[(nl + 1) * 136 + ml]     = __float2half(acc[mi][nj][1] + b1);
                T[nl * 136 + ml + 8]       = __float2half(acc[mi][nj][2] + b0);
                T[(nl + 1) * 136 + ml + 8] = __float2half(acc[mi][nj][3] + b1);
            }
        }
        __syncthreads();
        int b_ = m0 >> 11, s_ = m0 & (SEQ - 1);
        int nbase = n0 - 1536;
        __half* vt = (__half*)C2v;
        #pragma unroll
        for (int u = 0; u < 8; u++) {
            int idx = tid + u * 256;
            int r = idx >> 4, ch = idx & 15;
            int ng = nbase + r;
            int h = ng >> 6, d = ng & 63;
            uint4 val = *(uint4*)&T[r * 136 + ch * 8];
            *(uint4*)&vt[(((size_t)(b_ * NH + h) * DK + d) * SEQ + s_ + ch * 8)] = val;
        }
        return;
    }

    #pragma unroll
    for (int mi = 0; mi < 4; mi++) {
        #pragma unroll
        for (int nj = 0; nj < 4; nj++) {
            int m = m0 + wm * 64 + mi * 16 + g;
            int n = n0 + wn * 32 + nj * 8 + tig * 2;
            float b0 = bias[n], b1 = bias[n + 1];
            float v0 = acc[mi][nj][0] + b0, v1 = acc[mi][nj][1] + b1;
            float v2 = acc[mi][nj][2] + b0, v3 = acc[mi][nj][3] + b1;
            if (EPI == 1) {
                int isq = (n < 768);
                int nn = isq ? n : (n - 768);
                int h = nn >> 6, d = nn & 63;
                int b_ = m >> 11, s_ = m & (SEQ - 1);
                __half* dst = isq ? (__half*)C0v : (__half*)C1v;
                size_t base = (((size_t)(b_ * NH + h) * SEQ + s_) << 6) + d;
                *(__half2*)&dst[base] = __floats2half2_rn(v0, v1);
                size_t base2 = (((size_t)(b_ * NH + h) * SEQ + (s_ + 8)) << 6) + d;
                *(__half2*)&dst[base2] = __floats2half2_rn(v2, v3);
            } else {
                __half* C0 = (__half*)C0v;
                *(__half2*)&C0[(size_t)m * N + n] =
                    __floats2half2_rn(fmaxf(v0, 0.f), fmaxf(v1, 0.f));
                *(__half2*)&C0[(size_t)(m + 8) * N + n] =
                    __floats2half2_rn(fmaxf(v2, 0.f), fmaxf(v3, 0.f));
            }
        }
    }
}

// ========== fp16 mma GEMM 64x128, BK=64, 3 stages, 128 thr, 3 CTAs/SM (N=768) ==========
// (round-15 configuration: warp tile 64x32, best measured)
#define ATILE64_B 8192
#define STAGE64_B 24576
#define GEMM64_SMEM (3 * STAGE64_B)   // 72 KB

__global__ void __launch_bounds__(128, 3)
gemm_h64(const __half* __restrict__ A, const __half* __restrict__ Bt,
         const float* __restrict__ bias, const float* __restrict__ res,
         float* __restrict__ C0, int M, int N, int K) {
    extern __shared__ char smem[];
    uint32_t sb = smem_u32(smem);
    int tid = threadIdx.x;
    int lane = tid & 31, wn = tid >> 5;
    int g = lane >> 2, tig = lane & 3;
    int m0 = blockIdx.y * 64, n0 = blockIdx.x * 128;
    const __half* Ab = A  + (size_t)m0 * K;
    const __half* Bb = Bt + (size_t)n0 * K;
    const int NT = K / 64;

    const uint32_t rlA = (uint32_t)(lane & 15);
    const uint32_t klA = (uint32_t)(lane >> 4);
    const uint32_t rlB = (uint32_t)(wn * 32 + ((lane >> 4) << 3) + (lane & 7));
    const uint32_t klB = (uint32_t)((lane >> 3) & 1);

    float acc[4][4][4];
    #pragma unroll
    for (int i = 0; i < 4; i++)
        #pragma unroll
        for (int j = 0; j < 4; j++)
            #pragma unroll
            for (int r = 0; r < 4; r++) acc[i][j][r] = 0.f;

    auto LOAD = [&](int t) {
        int s = t % 3;
        uint32_t ab = sb + s * STAGE64_B;
        uint32_t bb = ab + ATILE64_B;
        int kt = t * 64;
        #pragma unroll
        for (int u = 0; u < 4; u++) {
            int idx = tid + u * 128;
            int r = idx >> 3, c = idx & 7;
            uint32_t sw = (uint32_t)r * 128 + (uint32_t)((c ^ (r & 7)) << 4);
            CP_ASYNC16(ab + sw, Ab + (size_t)r * K + kt + c * 8);
        }
        #pragma unroll
        for (int u = 0; u < 8; u++) {
            int idx = tid + u * 128;
            int r = idx >> 3, c = idx & 7;
            uint32_t sw = (uint32_t)r * 128 + (uint32_t)((c ^ (r & 7)) << 4);
            CP_ASYNC16(bb + sw, Bb + (size_t)r * K + kt + c * 8);
        }
        CP_COMMIT();
    };

    LOAD(0); LOAD(1);

    for (int t = 0; t < NT; t++) {
        if (t + 2 < NT) { CP_WAIT(1); } else { CP_WAIT(0); }
        __syncthreads();
        if (t + 2 < NT) LOAD(t + 2);

        int s = t % 3;
        uint32_t ab = sb + s * STAGE64_B;
        uint32_t bb = ab + ATILE64_B;

        #pragma unroll
        for (int ks = 0; ks < 4; ks++) {
            uint32_t afr[4][4], bfr[4][2];
            #pragma unroll
            for (int mi = 0; mi < 4; mi++) {
                uint32_t rl = rlA + (uint32_t)(mi * 16);
                uint32_t cl = (uint32_t)(2 * ks) | klA;
                ldsm4(afr[mi], ab + rl * 128 + ((cl ^ (rl & 7)) << 4));
            }
            #pragma unroll
            for (int j = 0; j < 2; j++) {
                uint32_t rl = rlB + (uint32_t)(j * 16);
                uint32_t cl = (uint32_t)(2 * ks) | klB;
                uint32_t tmp[4];
                ldsm4(tmp, bb + rl * 128 + ((cl ^ (rl & 7)) << 4));
                bfr[2*j][0]   = tmp[0]; bfr[2*j][1]   = tmp[1];
                bfr[2*j+1][0] = tmp[2]; bfr[2*j+1][1] = tmp[3];
            }
            #pragma unroll
            for (int mi = 0; mi < 4; mi++)
                #pragma unroll
                for (int nj = 0; nj < 4; nj++)
                    mma16h(acc[mi][nj], afr[mi], bfr[nj]);
        }
    }

    #pragma unroll
    for (int mi = 0; mi < 4; mi++) {
        #pragma unroll
        for (int nj = 0; nj < 4; nj++) {
            int m = m0 + mi * 16 + g;
            int n = n0 + wn * 32 + nj * 8 + tig * 2;
            float b0 = bias[n], b1 = bias[n + 1];
            float v0 = acc[mi][nj][0] + b0, v1 = acc[mi][nj][1] + b1;
            float v2 = acc[mi][nj][2] + b0, v3 = acc[mi][nj][3] + b1;
            float2 r0 = *(const float2*)&res[(size_t)m * N + n];
            float2 r1 = *(const float2*)&res[(size_t)(m + 8) * N + n];
            *(float2*)&C0[(size_t)m * N + n] = make_float2(v0 + r0.x, v1 + r0.y);
            *(float2*)&C0[(size_t)(m + 8) * N + n] = make_float2(v2 + r1.x, v3 + r1.y);
        }
    }
}

// ================= Flash attention: BQ=64, fast base-2 softmax, 4 CTAs/SM ==========
#define ATT_SMEM 40960

__global__ void __launch_bounds__(128, 4)
attn_h(const __half* __restrict__ Q, const __half* __restrict__ K,
       const __half* __restrict__ Vt, const int* __restrict__ mask,
       const int* __restrict__ mflag, __half* __restrict__ ctx) {
    extern __shared__ char sm[];
    uint32_t sb = smem_u32(sm);
    const uint32_t qs = sb;
    const uint32_t ks = sb + 8192;
    const uint32_t vs = sb + 24576;

    int tid = threadIdx.x;
    int lane = tid & 31, wr = tid >> 5;
    int g = lane >> 2, tig = lane & 3;
    int bh = blockIdx.y;
    int q0 = blockIdx.x * 64;
    const __half* Qb = Q  + (size_t)bh * SEQ * DK + (size_t)q0 * DK;
    const __half* Kb = K  + (size_t)bh * SEQ * DK;
    const __half* Vb = Vt + (size_t)bh * DK * SEQ;
    const int* flags = mflag + (blockIdx.x >> 1) * (SEQ / 64);

    const uint32_t rlQ = (uint32_t)(wr * 16 + (lane & 15));
    const uint32_t klQ = (uint32_t)(lane >> 4);
    const uint32_t rlB = (uint32_t)(((lane >> 4) << 3) + (lane & 7));
    const uint32_t klB = (uint32_t)((lane >> 3) & 1);

    #pragma unroll
    for (int u = 0; u < 4; u++) {
        int idx = tid + u * 128;
        int r = idx >> 3, c = idx & 7;
        uint32_t sw = (uint32_t)r * 128 + (uint32_t)((c ^ (r & 7)) * 16);
        CP_ASYNC16(qs + sw, Qb + (size_t)r * DK + c * 8);
    }
    auto LOADKV = [&](int buf, int t) {
        int k0 = t * 64;
        uint32_t kb = ks + (uint32_t)buf * 8192;
        uint32_t vb = vs + (uint32_t)buf * 8192;
        #pragma unroll
        for (int u = 0; u < 4; u++) {
            int idx = tid + u * 128;
            int r = idx >> 3, c = idx & 7;
            uint32_t sw = (uint32_t)r * 128 + (uint32_t)((c ^ (r & 7)) * 16);
            CP_ASYNC16(kb + sw, Kb + (size_t)(k0 + r) * DK + c * 8);
            CP_ASYNC16(vb + sw, Vb + (size_t)r * SEQ + k0 + c * 8);
        }
        CP_COMMIT();
    };
    LOADKV(0, 0);
    CP_WAIT(0);
    __syncthreads();

    uint32_t qfr[4][4];
    #pragma unroll
    for (int kc = 0; kc < 4; kc++) {
        uint32_t cl = (uint32_t)(2 * kc) | klQ;
        ldsm4(qfr[kc], qs + rlQ * 128 + ((cl ^ (rlQ & 7)) << 4));
    }

    float l0 = 0.f, l1 = 0.f;
    float o[8][4];
    #pragma unroll
    for (int j = 0; j < 8; j++)
        #pragma unroll
        for (int r = 0; r < 4; r++) o[j][r] = 0.f;

    const int row0 = wr * 16 + g;
    const int NT = SEQ / 64;

    for (int kt = 0; kt < NT; kt++) {
        if (kt + 1 < NT) LOADKV((kt + 1) & 1, kt + 1);

        int buf = kt & 1;
        uint32_t kbase = ks + (uint32_t)buf * 8192;
        uint32_t vbase = vs + (uint32_t)buf * 8192;

        float sacc[8][4];
        #pragma unroll
        for (int j = 0; j < 8; j++)
            #pragma unroll
            for (int r = 0; r < 4; r++) sacc[j][r] = 0.f;
        #pragma unroll
        for (int kc = 0; kc < 4; kc++) {
            uint32_t cl = (uint32_t)(2 * kc) | klB;
            #pragma unroll
            for (int j = 0; j < 4; j++) {
                uint32_t rl = rlB + (uint32_t)(j * 16);
                uint32_t tmp[4];
                ldsm4(tmp, kbase + rl * 128 + ((cl ^ (rl & 7)) << 4));
                uint32_t b0[2] = {tmp[0], tmp[1]}, b1[2] = {tmp[2], tmp[3]};
                mma16h(sacc[2*j],   qfr[kc], b0);
                mma16h(sacc[2*j+1], qfr[kc], b1);
            }
        }

        if (flags[kt]) {
            #pragma unroll
            for (int nj = 0; nj < 8; nj++) {
                float p0 = fexp2m(fmaf(sacc[nj][0], EXP_C1, EXP_C0));
                float p1 = fexp2m(fmaf(sacc[nj][1], EXP_C1, EXP_C0));
                float p2 = fexp2m(fmaf(sacc[nj][2], EXP_C1, EXP_C0));
                float p3 = fexp2m(fmaf(sacc[nj][3], EXP_C1, EXP_C0));
                l0 += p0 + p1; l1 += p2 + p3;
                sacc[nj][0] = p0; sacc[nj][1] = p1;
                sacc[nj][2] = p2; sacc[nj][3] = p3;
            }
        } else {
            int kg0 = kt * 64;
            const int* mr0 = mask + (size_t)(q0 + row0) * SEQ + kg0;
            const int* mr1 = mr0 + (size_t)8 * SEQ;
            #pragma unroll
            for (int nj = 0; nj < 8; nj++) {
                int c = nj * 8 + 2 * tig;
                int2 mk0 = *(const int2*)&mr0[c];
                int2 mk1 = *(const int2*)&mr1[c];
                float y0 = fmaxf(fmaf(sacc[nj][0], EXP_C1, EXP_C0), -126.f);
                float y1 = fmaxf(fmaf(sacc[nj][1], EXP_C1, EXP_C0), -126.f);
                float y2 = fmaxf(fmaf(sacc[nj][2], EXP_C1, EXP_C0), -126.f);
                float y3 = fmaxf(fmaf(sacc[nj][3], EXP_C1, EXP_C0), -126.f);
                float p0 = (mk0.x == 0) ? 0.f : fexp2m(y0);
                float p1 = (mk0.y == 0) ? 0.f : fexp2m(y1);
                float p2 = (mk1.x == 0) ? 0.f : fexp2m(y2);
                float p3 = (mk1.y == 0) ? 0.f : fexp2m(y3);
                l0 += p0 + p1; l1 += p2 + p3;
                sacc[nj][0] = p0; sacc[nj][1] = p1;
                sacc[nj][2] = p2; sacc[nj][3] = p3;
            }
        }

        #pragma unroll
        for (int kc = 0; kc < 4; kc++) {
            uint32_t afr[4];
            afr[0] = packh2(sacc[2*kc][0],   sacc[2*kc][1]);
            afr[1] = packh2(sacc[2*kc][2],   sacc[2*kc][3]);
            afr[2] = packh2(sacc[2*kc+1][0], sacc[2*kc+1][1]);
            afr[3] = packh2(sacc[2*kc+1][2], sacc[2*kc+1][3]);
            uint32_t cl = (uint32_t)(2 * kc) | klB;
            #pragma unroll
            for (int j = 0; j < 4; j++) {
                uint32_t rl = rlB + (uint32_t)(j * 16);
                uint32_t tmp[4];
                ldsm4(tmp, vbase + rl * 128 + ((cl ^ (rl & 7)) << 4));
                uint32_t b0[2] = {tmp[0], tmp[1]}, b1[2] = {tmp[2], tmp[3]};
                mma16h(o[2*j],   afr, b0);
                mma16h(o[2*j+1], afr, b1);
            }
        }

        if (kt + 1 < NT) { CP_WAIT(0); __syncthreads(); }
    }

    l0 += __shfl_xor_sync(0xffffffffu, l0, 1);
    l0 += __shfl_xor_sync(0xffffffffu, l0, 2);
    l1 += __shfl_xor_sync(0xffffffffu, l1, 1);
    l1 += __shfl_xor_sync(0xffffffffu, l1, 2);

    float inv0 = 1.f / l0, inv1 = 1.f / l1;
    int b_ = bh / NH, h_ = bh % NH;
    __half* base0 = ctx + (size_t)(b_ * SEQ + q0 + row0) * DM + h_ * 64;
    __half* base1 = base0 + (size_t)8 * DM;
    #pragma unroll
    for (int nj = 0; nj < 8; nj++) {
        int c = nj * 8 + 2 * tig;
        *(__half2*)&base0[c] = __floats2half2_rn(o[nj][0] * inv0, o[nj][1] * inv0);
        *(__half2*)&base1[c] = __floats2half2_rn(o[nj][2] * inv1, o[nj][3] * inv1);
    }
}

// ---------------- launch ----------------
extern "C" void kernel_launch(void* const* d_in, const int* in_sizes, int n_in,
                              void* d_out, int out_size) {
    (void)in_sizes; (void)n_in; (void)out_size;
    const float* x    = (const float*)d_in[0];
    const int*   mask = (const int*)  d_in[1];
    const float* wq = (const float*)d_in[2];
    const float* bq = (const float*)d_in[3];
    const float* wk = (const float*)d_in[4];
    const float* bk = (const float*)d_in[5];
    const float* wv = (const float*)d_in[6];
    const float* bv = (const float*)d_in[7];
    const float* wo = (const float*)d_in[8];
    const float* bo = (const float*)d_in[9];
    const float* w1 = (const float*)d_in[10];
    const float* b1 = (const float*)d_in[11];
    const float* w2 = (const float*)d_in[12];
    const float* b2 = (const float*)d_in[13];
    const float* alpha1 = (const float*)d_in[14];
    const float* beta1  = (const float*)d_in[15];
    const float* alpha2 = (const float*)d_in[16];
    const float* beta2  = (const float*)d_in[17];
    float* out = (float*)d_out;

    __half *xnh, *qh, *kh, *vth, *ctxh, *ffh, *wth;
    float *x1, *bqkv;
    int* mflag;
    cudaGetSymbolAddress((void**)&xnh,  g_xnh);
    cudaGetSymbolAddress((void**)&qh,   g_qh);
    cudaGetSymbolAddress((void**)&kh,   g_kh);
    cudaGetSymbolAddress((void**)&vth,  g_vth);
    cudaGetSymbolAddress((void**)&ctxh, g_ctxh);
    cudaGetSymbolAddress((void**)&x1,   g_x1);
    cudaGetSymbolAddress((void**)&ffh,  g_ffh);
    cudaGetSymbolAddress((void**)&wth,  g_wth);
    cudaGetSymbolAddress((void**)&bqkv, g_bqkv);
    cudaGetSymbolAddress((void**)&mflag, g_mflag);

    cudaFuncSetAttribute(attn_h, cudaFuncAttributeMaxDynamicSharedMemorySize, ATT_SMEM);
    cudaFuncSetAttribute(gemm_h<1>, cudaFuncAttributeMaxDynamicSharedMemorySize, GEMM_SMEM);
    cudaFuncSetAttribute(gemm_h<3>, cudaFuncAttributeMaxDynamicSharedMemorySize, GEMM_SMEM);
    cudaFuncSetAttribute(gemm_h64, cudaFuncAttributeMaxDynamicSharedMemorySize, GEMM64_SMEM);

    prep_all<<<PREP_BLOCKS, 256>>>(x, alpha1, beta1, mask,                 // 1
        wq, wk, wv, wo, w1, w2, bq, bk, bv, wth, bqkv, mflag, xnh);

    gemm_h<1><<<dim3(2304/128, ROWS/128), 256, GEMM_SMEM>>>(               // 2
        xnh, wth + WT_QKV, bqkv, nullptr, qh, kh, vth, ROWS, 2304, DM);

    attn_h<<<dim3(SEQ/64, BS_ * NH), 128, ATT_SMEM>>>(                     // 3
        qh, kh, vth, mask, mflag, ctxh);

    gemm_h64<<<dim3(DM/128, ROWS/64), 128, GEMM64_SMEM>>>(                 // 4
        ctxh, wth + WT_O, bo, x, x1, ROWS, DM, DM);

    ln_kernel<<<ROWS, 256>>>(x1, alpha2, beta2, xnh);                      // 5

    gemm_h<3><<<dim3(FF/128, ROWS/128), 256, GEMM_SMEM>>>(                 // 6
        xnh, wth + WT_1, b1, nullptr, ffh, nullptr, nullptr, ROWS, FF, DM);

    gemm_h64<<<dim3(DM/128, ROWS/64), 128, GEMM64_SMEM>>>(                 // 7
        ffh, wth + WT_2, b2, x1, out, ROWS, DM, FF);
}